// round 2
// baseline (speedup 1.0000x reference)
#include <cuda_runtime.h>
#include <math.h>

// ---------------------------------------------------------------------------
// Fused NeRF MLP, fp32, f32x2-packed FMA baseline.
//   N = 131072 points, W = 256.
//   Per CTA: 64 rows. Activations in SMEM: [64][344] = [e_pts(84) | h(256)].
//   Skip-concat at layer 5 is free (buffer layout == concat layout).
//   Output: d_out[0..N) = alpha, d_out[N..4N) = rgb row-major [N,3].
// ---------------------------------------------------------------------------

#define NPTS   131072
#define MTILE  64
#define NTH    256
#define HSTR   344     // floats per row of h buffer (>=340, mult of 8)
#define EVSTR  56      // floats per row of e_view buffer (>=54, mult of 8)

// ---- f32x2 packed helpers (FFMA2 is PTX-only; ptxas won't auto-fuse) -------
__device__ __forceinline__ unsigned long long pk2(float lo, float hi) {
    unsigned long long r;
    asm("mov.b64 %0, {%1,%2};" : "=l"(r)
        : "r"(__float_as_uint(lo)), "r"(__float_as_uint(hi)));
    return r;
}
__device__ __forceinline__ void upk2(unsigned long long v, float& lo, float& hi) {
    unsigned int l, h;
    asm("mov.b64 {%0,%1}, %2;" : "=r"(l), "=r"(h) : "l"(v));
    lo = __uint_as_float(l);
    hi = __uint_as_float(h);
}
__device__ __forceinline__ unsigned long long ffma2(unsigned long long a,
                                                    unsigned long long b,
                                                    unsigned long long c) {
    unsigned long long d;
    asm("fma.rn.f32x2 %0, %1, %2, %3;" : "=l"(d) : "l"(a), "l"(b), "l"(c));
    return d;
}

// ---------------------------------------------------------------------------
// dense: sm_out[64][OUT] = act( sm_in[64][K] @ W[K][OUT] + B[OUT] )
// Thread tile: 8 cols x RPT rows, packed f32x2 accumulators (col pairs).
// OUT=256 -> RPT=8 (32 col-groups x 8 row-groups = 256 threads)
// OUT=128 -> RPT=4 (16 col-groups x 16 row-groups)
// noinline: keep I$ footprint small across 11 call sites.
// ---------------------------------------------------------------------------
template<int OUT, int RPT>
__device__ __noinline__ void dense(const float* __restrict__ sm_in, int in_stride, int K,
                                   const float* __restrict__ W, const float* __restrict__ B,
                                   float* __restrict__ sm_out, int out_stride, bool do_relu)
{
    constexpr int CG = OUT / 8;
    const int tid = threadIdx.x;
    const int j0  = (tid % CG) * 8;
    const int r0  = (tid / CG) * RPT;

    unsigned long long acc[RPT][4];
    {
        float4 bA = *reinterpret_cast<const float4*>(B + j0);
        float4 bB = *reinterpret_cast<const float4*>(B + j0 + 4);
        unsigned long long p0 = pk2(bA.x, bA.y), p1 = pk2(bA.z, bA.w);
        unsigned long long p2 = pk2(bB.x, bB.y), p3 = pk2(bB.z, bB.w);
        #pragma unroll
        for (int r = 0; r < RPT; r++) {
            acc[r][0] = p0; acc[r][1] = p1; acc[r][2] = p2; acc[r][3] = p3;
        }
    }

    const int Kmain = K & ~3;
    int k = 0;
    #pragma unroll 2
    for (; k < Kmain; k += 4) {
        // 4 weight rows, 8 cols each; double2 loads give pre-packed f32x2 pairs.
        unsigned long long w[4][4];
        #pragma unroll
        for (int kk = 0; kk < 4; kk++) {
            const double2* wp =
                reinterpret_cast<const double2*>(W + (size_t)(k + kk) * OUT + j0);
            double2 wa = wp[0];
            double2 wb = wp[1];
            w[kk][0] = __double_as_longlong(wa.x);
            w[kk][1] = __double_as_longlong(wa.y);
            w[kk][2] = __double_as_longlong(wb.x);
            w[kk][3] = __double_as_longlong(wb.y);
        }
        #pragma unroll
        for (int r = 0; r < RPT; r++) {
            float4 h4 = *reinterpret_cast<const float4*>(sm_in + (r0 + r) * in_stride + k);
            unsigned long long hd;
            hd = pk2(h4.x, h4.x);
            acc[r][0] = ffma2(hd, w[0][0], acc[r][0]);
            acc[r][1] = ffma2(hd, w[0][1], acc[r][1]);
            acc[r][2] = ffma2(hd, w[0][2], acc[r][2]);
            acc[r][3] = ffma2(hd, w[0][3], acc[r][3]);
            hd = pk2(h4.y, h4.y);
            acc[r][0] = ffma2(hd, w[1][0], acc[r][0]);
            acc[r][1] = ffma2(hd, w[1][1], acc[r][1]);
            acc[r][2] = ffma2(hd, w[1][2], acc[r][2]);
            acc[r][3] = ffma2(hd, w[1][3], acc[r][3]);
            hd = pk2(h4.z, h4.z);
            acc[r][0] = ffma2(hd, w[2][0], acc[r][0]);
            acc[r][1] = ffma2(hd, w[2][1], acc[r][1]);
            acc[r][2] = ffma2(hd, w[2][2], acc[r][2]);
            acc[r][3] = ffma2(hd, w[2][3], acc[r][3]);
            hd = pk2(h4.w, h4.w);
            acc[r][0] = ffma2(hd, w[3][0], acc[r][0]);
            acc[r][1] = ffma2(hd, w[3][1], acc[r][1]);
            acc[r][2] = ffma2(hd, w[3][2], acc[r][2]);
            acc[r][3] = ffma2(hd, w[3][3], acc[r][3]);
        }
    }
    // scalar k tail (views layer: K=310 -> 2 tail rows)
    for (; k < K; k++) {
        float4 wa = *reinterpret_cast<const float4*>(W + (size_t)k * OUT + j0);
        float4 wb = *reinterpret_cast<const float4*>(W + (size_t)k * OUT + j0 + 4);
        unsigned long long w0 = pk2(wa.x, wa.y), w1 = pk2(wa.z, wa.w);
        unsigned long long w2 = pk2(wb.x, wb.y), w3 = pk2(wb.z, wb.w);
        #pragma unroll
        for (int r = 0; r < RPT; r++) {
            float h = sm_in[(r0 + r) * in_stride + k];
            unsigned long long hd = pk2(h, h);
            acc[r][0] = ffma2(hd, w0, acc[r][0]);
            acc[r][1] = ffma2(hd, w1, acc[r][1]);
            acc[r][2] = ffma2(hd, w2, acc[r][2]);
            acc[r][3] = ffma2(hd, w3, acc[r][3]);
        }
    }

    __syncthreads();   // all reads of sm_in complete before anyone writes sm_out
    #pragma unroll
    for (int r = 0; r < RPT; r++) {
        float o[8];
        upk2(acc[r][0], o[0], o[1]);
        upk2(acc[r][1], o[2], o[3]);
        upk2(acc[r][2], o[4], o[5]);
        upk2(acc[r][3], o[6], o[7]);
        if (do_relu) {
            #pragma unroll
            for (int i = 0; i < 8; i++) o[i] = fmaxf(o[i], 0.0f);
        }
        float* op = sm_out + (r0 + r) * out_stride + j0;
        *reinterpret_cast<float4*>(op)     = make_float4(o[0], o[1], o[2], o[3]);
        *reinterpret_cast<float4*>(op + 4) = make_float4(o[4], o[5], o[6], o[7]);
    }
    __syncthreads();   // writes visible before next layer reads
}

struct KParams {
    const float *input_pts, *input_views, *input_pls;
    const float *pw[8], *pb[8];
    const float *views_w, *views_b;
    const float *feature_w, *feature_b;
    const float *alpha_w, *alpha_b;
    const float *rgb_w, *rgb_b;
    float *out;
};

extern __shared__ float smem[];

__global__ void __launch_bounds__(NTH, 1) nerf_fused(KParams P)
{
    float* sm_h  = smem;                          // [64][344]: [e_pts | h]
    float* sm_ev = smem + MTILE * HSTR;           // [64][56] : e_view
    float* sm_hv = sm_ev + MTILE * EVSTR;         // [64][128]: views-layer out

    const int tid = threadIdx.x;
    const int blk = blockIdx.x;

    // ---- positional encodings -------------------------------------------
    if (tid < MTILE) {
        const int g = blk * MTILE + tid;
        float4 p = *reinterpret_cast<const float4*>(P.input_pts + (size_t)g * 4);
        float* row = sm_h + tid * HSTR;
        float xs[4] = {p.x, p.y, p.z, p.w};
        #pragma unroll
        for (int d = 0; d < 4; d++) row[d] = xs[d];
        #pragma unroll
        for (int d = 0; d < 4; d++) {
            float f = 1.0f;
            #pragma unroll
            for (int l = 0; l < 10; l++) {
                float s, c;
                sincosf(xs[d] * f, &s, &c);
                row[4 + d * 20 + l * 2]     = s;
                row[4 + d * 20 + l * 2 + 1] = c;
                f *= 2.0f;
            }
        }
    } else if (tid < 2 * MTILE) {
        const int r = tid - MTILE;
        const int g = blk * MTILE + r;
        float xs[6];
        xs[0] = P.input_views[(size_t)g * 3 + 0];
        xs[1] = P.input_views[(size_t)g * 3 + 1];
        xs[2] = P.input_views[(size_t)g * 3 + 2];
        xs[3] = P.input_pls[(size_t)g * 3 + 0];
        xs[4] = P.input_pls[(size_t)g * 3 + 1];
        xs[5] = P.input_pls[(size_t)g * 3 + 2];
        float* row = sm_ev + r * EVSTR;
        #pragma unroll
        for (int d = 0; d < 6; d++) row[d] = xs[d];
        #pragma unroll
        for (int d = 0; d < 6; d++) {
            float f = 1.0f;
            #pragma unroll
            for (int l = 0; l < 4; l++) {
                float s, c;
                sincosf(xs[d] * f, &s, &c);
                row[6 + d * 8 + l * 2]     = s;
                row[6 + d * 8 + l * 2 + 1] = c;
                f *= 2.0f;
            }
        }
    }
    __syncthreads();

    // ---- pts MLP ----------------------------------------------------------
    // layer 0: e_pts(84) -> h(256) at cols [84..340)
    dense<256, 8>(sm_h, HSTR, 84, P.pw[0], P.pb[0], sm_h + 84, HSTR, true);
    // layers 1..4: 256 -> 256
    #pragma unroll 1
    for (int i = 1; i <= 4; i++)
        dense<256, 8>(sm_h + 84, HSTR, 256, P.pw[i], P.pb[i], sm_h + 84, HSTR, true);
    // layer 5: skip-concat [e_pts | h4] = cols [0..340) -> 256
    dense<256, 8>(sm_h, HSTR, 340, P.pw[5], P.pb[5], sm_h + 84, HSTR, true);
    // layers 6,7
    dense<256, 8>(sm_h + 84, HSTR, 256, P.pw[6], P.pb[6], sm_h + 84, HSTR, true);
    dense<256, 8>(sm_h + 84, HSTR, 256, P.pw[7], P.pb[7], sm_h + 84, HSTR, true);

    // ---- alpha = h @ alpha_w + alpha_b (before feature overwrites buffer) --
    if (tid < MTILE) {
        const float* hr = sm_h + tid * HSTR + 84;
        float a = P.alpha_b[0];
        #pragma unroll 4
        for (int kk = 0; kk < 256; kk += 4) {
            float4 h4 = *reinterpret_cast<const float4*>(hr + kk);
            float4 w4 = *reinterpret_cast<const float4*>(P.alpha_w + kk);
            a += h4.x * w4.x + h4.y * w4.y + h4.z * w4.z + h4.w * w4.w;
        }
        P.out[blk * MTILE + tid] = a;
    }

    // ---- feature (no relu) -> cols [0..256); internal barrier protects
    //      the overlap with h reads (and the alpha reads above).
    dense<256, 8>(sm_h + 84, HSTR, 256, P.feature_w, P.feature_b, sm_h, HSTR, false);

    // ---- append e_view at cols [256..310) --------------------------------
    for (int idx = tid; idx < MTILE * 54; idx += NTH) {
        int r = idx / 54;
        int c = idx - r * 54;
        sm_h[r * HSTR + 256 + c] = sm_ev[r * EVSTR + c];
    }
    __syncthreads();

    // ---- views layer: [feature|e_view](310) -> hv(128), relu --------------
    dense<128, 4>(sm_h, HSTR, 310, P.views_w, P.views_b, sm_hv, 128, true);

    // ---- rgb = hv @ rgb_w + rgb_b ------------------------------------------
    if (tid < MTILE * 3) {
        int r = tid / 3;
        int c = tid - r * 3;
        const float* hv = sm_hv + r * 128;
        float a = P.rgb_b[c];
        #pragma unroll 8
        for (int kk = 0; kk < 128; kk++) a += hv[kk] * P.rgb_w[kk * 3 + c];
        P.out[(size_t)NPTS + (size_t)(blk * MTILE + r) * 3 + c] = a;
    }
}

extern "C" void kernel_launch(void* const* d_in, const int* in_sizes, int n_in,
                              void* d_out, int out_size)
{
    (void)in_sizes; (void)n_in; (void)out_size;
    KParams P;
    P.input_pts   = (const float*)d_in[0];
    P.input_views = (const float*)d_in[1];
    P.input_pls   = (const float*)d_in[2];
    for (int i = 0; i < 8; i++) {
        P.pw[i] = (const float*)d_in[3 + 2 * i];
        P.pb[i] = (const float*)d_in[4 + 2 * i];
    }
    P.views_w   = (const float*)d_in[19];
    P.views_b   = (const float*)d_in[20];
    P.feature_w = (const float*)d_in[21];
    P.feature_b = (const float*)d_in[22];
    P.alpha_w   = (const float*)d_in[23];
    P.alpha_b   = (const float*)d_in[24];
    P.rgb_w     = (const float*)d_in[25];
    P.rgb_b     = (const float*)d_in[26];
    P.out       = (float*)d_out;

    const int smem_bytes = (MTILE * HSTR + MTILE * EVSTR + MTILE * 128) * (int)sizeof(float);
    cudaFuncSetAttribute(nerf_fused, cudaFuncAttributeMaxDynamicSharedMemorySize, smem_bytes);
    nerf_fused<<<NPTS / MTILE, NTH, smem_bytes>>>(P);
}

// round 3
// speedup vs baseline: 1.0569x; 1.0569x over previous
#include <cuda_runtime.h>
#include <math.h>

// ---------------------------------------------------------------------------
// Fused NeRF MLP, fp32, f32x2-packed FMA baseline.
//   N = 131072 points, W = 256.
//   Per CTA: 64 rows. Activations in SMEM: [64][344] = [e_pts(84) | h(256)].
//   Skip-concat at layer 5 is free (buffer layout == concat layout).
//   Output: d_out[0..N) = alpha, d_out[N..4N) = rgb row-major [N,3].
// ---------------------------------------------------------------------------

#define NPTS   131072
#define MTILE  64
#define NTH    256
#define HSTR   344     // floats per row of h buffer (>=340, mult of 8)
#define EVSTR  56      // floats per row of e_view buffer (>=54, mult of 8)

// ---- f32x2 packed helpers (FFMA2 is PTX-only; ptxas won't auto-fuse) -------
__device__ __forceinline__ unsigned long long pk2(float lo, float hi) {
    unsigned long long r;
    asm("mov.b64 %0, {%1,%2};" : "=l"(r)
        : "r"(__float_as_uint(lo)), "r"(__float_as_uint(hi)));
    return r;
}
__device__ __forceinline__ void upk2(unsigned long long v, float& lo, float& hi) {
    unsigned int l, h;
    asm("mov.b64 {%0,%1}, %2;" : "=r"(l), "=r"(h) : "l"(v));
    lo = __uint_as_float(l);
    hi = __uint_as_float(h);
}
__device__ __forceinline__ unsigned long long ffma2(unsigned long long a,
                                                    unsigned long long b,
                                                    unsigned long long c) {
    unsigned long long d;
    asm("fma.rn.f32x2 %0, %1, %2, %3;" : "=l"(d) : "l"(a), "l"(b), "l"(c));
    return d;
}

// ---------------------------------------------------------------------------
// dense: sm_out[64][OUT] = act( sm_in[64][K] @ W[K][OUT] + B[OUT] )
// Thread tile: 8 cols x RPT rows, packed f32x2 accumulators (col pairs).
// OUT=256 -> RPT=8 (32 col-groups x 8 row-groups = 256 threads)
// OUT=128 -> RPT=4 (16 col-groups x 16 row-groups)
// noinline: keep I$ footprint small across 11 call sites.
// ---------------------------------------------------------------------------
template<int OUT, int RPT>
__device__ __noinline__ void dense(const float* __restrict__ sm_in, int in_stride, int K,
                                   const float* __restrict__ W, const float* __restrict__ B,
                                   float* __restrict__ sm_out, int out_stride, bool do_relu)
{
    constexpr int CG = OUT / 8;
    const int tid = threadIdx.x;
    const int j0  = (tid % CG) * 8;
    const int r0  = (tid / CG) * RPT;

    unsigned long long acc[RPT][4];
    {
        float4 bA = *reinterpret_cast<const float4*>(B + j0);
        float4 bB = *reinterpret_cast<const float4*>(B + j0 + 4);
        unsigned long long p0 = pk2(bA.x, bA.y), p1 = pk2(bA.z, bA.w);
        unsigned long long p2 = pk2(bB.x, bB.y), p3 = pk2(bB.z, bB.w);
        #pragma unroll
        for (int r = 0; r < RPT; r++) {
            acc[r][0] = p0; acc[r][1] = p1; acc[r][2] = p2; acc[r][3] = p3;
        }
    }

    const int Kmain = K & ~3;
    int k = 0;
    #pragma unroll 2
    for (; k < Kmain; k += 4) {
        // 4 weight rows, 8 cols each; double2 loads give pre-packed f32x2 pairs.
        unsigned long long w[4][4];
        #pragma unroll
        for (int kk = 0; kk < 4; kk++) {
            const double2* wp =
                reinterpret_cast<const double2*>(W + (size_t)(k + kk) * OUT + j0);
            double2 wa = wp[0];
            double2 wb = wp[1];
            w[kk][0] = __double_as_longlong(wa.x);
            w[kk][1] = __double_as_longlong(wa.y);
            w[kk][2] = __double_as_longlong(wb.x);
            w[kk][3] = __double_as_longlong(wb.y);
        }
        #pragma unroll
        for (int r = 0; r < RPT; r++) {
            float4 h4 = *reinterpret_cast<const float4*>(sm_in + (r0 + r) * in_stride + k);
            unsigned long long hd;
            hd = pk2(h4.x, h4.x);
            acc[r][0] = ffma2(hd, w[0][0], acc[r][0]);
            acc[r][1] = ffma2(hd, w[0][1], acc[r][1]);
            acc[r][2] = ffma2(hd, w[0][2], acc[r][2]);
            acc[r][3] = ffma2(hd, w[0][3], acc[r][3]);
            hd = pk2(h4.y, h4.y);
            acc[r][0] = ffma2(hd, w[1][0], acc[r][0]);
            acc[r][1] = ffma2(hd, w[1][1], acc[r][1]);
            acc[r][2] = ffma2(hd, w[1][2], acc[r][2]);
            acc[r][3] = ffma2(hd, w[1][3], acc[r][3]);
            hd = pk2(h4.z, h4.z);
            acc[r][0] = ffma2(hd, w[2][0], acc[r][0]);
            acc[r][1] = ffma2(hd, w[2][1], acc[r][1]);
            acc[r][2] = ffma2(hd, w[2][2], acc[r][2]);
            acc[r][3] = ffma2(hd, w[2][3], acc[r][3]);
            hd = pk2(h4.w, h4.w);
            acc[r][0] = ffma2(hd, w[3][0], acc[r][0]);
            acc[r][1] = ffma2(hd, w[3][1], acc[r][1]);
            acc[r][2] = ffma2(hd, w[3][2], acc[r][2]);
            acc[r][3] = ffma2(hd, w[3][3], acc[r][3]);
        }
    }
    // scalar k tail (views layer: K=310 -> 2 tail rows)
    for (; k < K; k++) {
        float4 wa = *reinterpret_cast<const float4*>(W + (size_t)k * OUT + j0);
        float4 wb = *reinterpret_cast<const float4*>(W + (size_t)k * OUT + j0 + 4);
        unsigned long long w0 = pk2(wa.x, wa.y), w1 = pk2(wa.z, wa.w);
        unsigned long long w2 = pk2(wb.x, wb.y), w3 = pk2(wb.z, wb.w);
        #pragma unroll
        for (int r = 0; r < RPT; r++) {
            float h = sm_in[(r0 + r) * in_stride + k];
            unsigned long long hd = pk2(h, h);
            acc[r][0] = ffma2(hd, w0, acc[r][0]);
            acc[r][1] = ffma2(hd, w1, acc[r][1]);
            acc[r][2] = ffma2(hd, w2, acc[r][2]);
            acc[r][3] = ffma2(hd, w3, acc[r][3]);
        }
    }

    __syncthreads();   // all reads of sm_in complete before anyone writes sm_out
    #pragma unroll
    for (int r = 0; r < RPT; r++) {
        float o[8];
        upk2(acc[r][0], o[0], o[1]);
        upk2(acc[r][1], o[2], o[3]);
        upk2(acc[r][2], o[4], o[5]);
        upk2(acc[r][3], o[6], o[7]);
        if (do_relu) {
            #pragma unroll
            for (int i = 0; i < 8; i++) o[i] = fmaxf(o[i], 0.0f);
        }
        float* op = sm_out + (r0 + r) * out_stride + j0;
        *reinterpret_cast<float4*>(op)     = make_float4(o[0], o[1], o[2], o[3]);
        *reinterpret_cast<float4*>(op + 4) = make_float4(o[4], o[5], o[6], o[7]);
    }
    __syncthreads();   // writes visible before next layer reads
}

struct KParams {
    const float *input_pts, *input_views, *input_pls;
    const float *pw[8], *pb[8];
    const float *views_w, *views_b;
    const float *feature_w, *feature_b;
    const float *alpha_w, *alpha_b;
    const float *rgb_w, *rgb_b;
    float *out;
};

extern __shared__ float smem[];

__global__ void __launch_bounds__(NTH, 1) nerf_fused(KParams P)
{
    float* sm_h  = smem;                          // [64][344]: [e_pts | h]
    float* sm_ev = smem + MTILE * HSTR;           // [64][56] : e_view
    float* sm_hv = sm_ev + MTILE * EVSTR;         // [64][128]: views-layer out

    const int tid = threadIdx.x;
    const int blk = blockIdx.x;

    // ---- positional encodings -------------------------------------------
    if (tid < MTILE) {
        const int g = blk * MTILE + tid;
        float4 p = *reinterpret_cast<const float4*>(P.input_pts + (size_t)g * 4);
        float* row = sm_h + tid * HSTR;
        float xs[4] = {p.x, p.y, p.z, p.w};
        #pragma unroll
        for (int d = 0; d < 4; d++) row[d] = xs[d];
        #pragma unroll
        for (int d = 0; d < 4; d++) {
            float f = 1.0f;
            #pragma unroll
            for (int l = 0; l < 10; l++) {
                float s, c;
                sincosf(xs[d] * f, &s, &c);
                row[4 + d * 20 + l * 2]     = s;
                row[4 + d * 20 + l * 2 + 1] = c;
                f *= 2.0f;
            }
        }
    } else if (tid < 2 * MTILE) {
        const int r = tid - MTILE;
        const int g = blk * MTILE + r;
        float xs[6];
        xs[0] = P.input_views[(size_t)g * 3 + 0];
        xs[1] = P.input_views[(size_t)g * 3 + 1];
        xs[2] = P.input_views[(size_t)g * 3 + 2];
        xs[3] = P.input_pls[(size_t)g * 3 + 0];
        xs[4] = P.input_pls[(size_t)g * 3 + 1];
        xs[5] = P.input_pls[(size_t)g * 3 + 2];
        float* row = sm_ev + r * EVSTR;
        #pragma unroll
        for (int d = 0; d < 6; d++) row[d] = xs[d];
        #pragma unroll
        for (int d = 0; d < 6; d++) {
            float f = 1.0f;
            #pragma unroll
            for (int l = 0; l < 4; l++) {
                float s, c;
                sincosf(xs[d] * f, &s, &c);
                row[6 + d * 8 + l * 2]     = s;
                row[6 + d * 8 + l * 2 + 1] = c;
                f *= 2.0f;
            }
        }
    }
    __syncthreads();

    // ---- pts MLP ----------------------------------------------------------
    // layer 0: e_pts(84) -> h(256) at cols [84..340)
    dense<256, 8>(sm_h, HSTR, 84, P.pw[0], P.pb[0], sm_h + 84, HSTR, true);
    // layers 1..4: 256 -> 256
    #pragma unroll 1
    for (int i = 1; i <= 4; i++)
        dense<256, 8>(sm_h + 84, HSTR, 256, P.pw[i], P.pb[i], sm_h + 84, HSTR, true);
    // layer 5: skip-concat [e_pts | h4] = cols [0..340) -> 256
    dense<256, 8>(sm_h, HSTR, 340, P.pw[5], P.pb[5], sm_h + 84, HSTR, true);
    // layers 6,7
    dense<256, 8>(sm_h + 84, HSTR, 256, P.pw[6], P.pb[6], sm_h + 84, HSTR, true);
    dense<256, 8>(sm_h + 84, HSTR, 256, P.pw[7], P.pb[7], sm_h + 84, HSTR, true);

    // ---- alpha = h @ alpha_w + alpha_b (before feature overwrites buffer) --
    if (tid < MTILE) {
        const float* hr = sm_h + tid * HSTR + 84;
        float a = P.alpha_b[0];
        #pragma unroll 4
        for (int kk = 0; kk < 256; kk += 4) {
            float4 h4 = *reinterpret_cast<const float4*>(hr + kk);
            float4 w4 = *reinterpret_cast<const float4*>(P.alpha_w + kk);
            a += h4.x * w4.x + h4.y * w4.y + h4.z * w4.z + h4.w * w4.w;
        }
        P.out[blk * MTILE + tid] = a;
    }

    // ---- feature (no relu) -> cols [0..256); internal barrier protects
    //      the overlap with h reads (and the alpha reads above).
    dense<256, 8>(sm_h + 84, HSTR, 256, P.feature_w, P.feature_b, sm_h, HSTR, false);

    // ---- append e_view at cols [256..310) --------------------------------
    for (int idx = tid; idx < MTILE * 54; idx += NTH) {
        int r = idx / 54;
        int c = idx - r * 54;
        sm_h[r * HSTR + 256 + c] = sm_ev[r * EVSTR + c];
    }
    __syncthreads();

    // ---- views layer: [feature|e_view](310) -> hv(128), relu --------------
    dense<128, 4>(sm_h, HSTR, 310, P.views_w, P.views_b, sm_hv, 128, true);

    // ---- rgb = hv @ rgb_w + rgb_b ------------------------------------------
    if (tid < MTILE * 3) {
        int r = tid / 3;
        int c = tid - r * 3;
        const float* hv = sm_hv + r * 128;
        float a = P.rgb_b[c];
        #pragma unroll 8
        for (int kk = 0; kk < 128; kk++) a += hv[kk] * P.rgb_w[kk * 3 + c];
        P.out[(size_t)NPTS + (size_t)(blk * MTILE + r) * 3 + c] = a;
    }
}

extern "C" void kernel_launch(void* const* d_in, const int* in_sizes, int n_in,
                              void* d_out, int out_size)
{
    (void)in_sizes; (void)n_in; (void)out_size;
    KParams P;
    P.input_pts   = (const float*)d_in[0];
    P.input_views = (const float*)d_in[1];
    P.input_pls   = (const float*)d_in[2];
    for (int i = 0; i < 8; i++) {
        P.pw[i] = (const float*)d_in[3 + 2 * i];
        P.pb[i] = (const float*)d_in[4 + 2 * i];
    }
    P.views_w   = (const float*)d_in[19];
    P.views_b   = (const float*)d_in[20];
    P.feature_w = (const float*)d_in[21];
    P.feature_b = (const float*)d_in[22];
    P.alpha_w   = (const float*)d_in[23];
    P.alpha_b   = (const float*)d_in[24];
    P.rgb_w     = (const float*)d_in[25];
    P.rgb_b     = (const float*)d_in[26];
    P.out       = (float*)d_out;

    const int smem_bytes = (MTILE * HSTR + MTILE * EVSTR + MTILE * 128) * (int)sizeof(float);
    cudaFuncSetAttribute(nerf_fused, cudaFuncAttributeMaxDynamicSharedMemorySize, smem_bytes);
    nerf_fused<<<NPTS / MTILE, NTH, smem_bytes>>>(P);
}